// round 12
// baseline (speedup 1.0000x reference)
#include <cuda_runtime.h>
#include <math.h>
#include <stdint.h>

#define Nn    4096
#define CAP   160                  // per-node edge capacity (mean deg ~41)
#define GAMMA_F 0.99f
#define EPSF  1.1920929e-07f

// ---- iterate kernel shape ----
#define NB    64                   // blocks (1/SM)
#define ITHR  512
#define NPB   (Nn / NB)            // 64 nodes per block
#define TPN   (ITHR / NPB)         // 8 threads per node

// ---- dynamic smem layout for iterate (bytes) ----
#define OFF_U     0                      // 16384
#define OFF_W     16384                  // 64*CAP*4 = 40960
#define OFF_COLS  57344                  // 64*CAP*2 = 20480
#define OFF_R     77824                  // 256
#define OFF_S     78080
#define OFF_DINV  78336
#define OFF_V     78592
#define OFF_CNT   78848
#define OFF_WA    79104
#define OFF_BA    79168
#define ISMEM     79232

// ---- scratch (static device globals; no allocations anywhere) ----
__device__ unsigned short g_colsU[(size_t)Nn * CAP];
__device__ int    g_cnt[Nn];
__device__ float  g_r[Nn];
__device__ float  g_s[Nn];
__device__ float2 g_de[Nn];            // (dinv_j, dinv_j*(s_j+bemb))
__device__ float  g_u[2][Nn];          // published u, double-buffered
__device__ volatile int g_flag[NB];    // symmetric barrier flags
__device__ int    g_done;              // end-of-kernel reset protocol

// ==================================================================
// Kernel 1: adjacency scan + feature computation. One block per row.
// 256 threads * 4 float4 = 1024 float4 = full 4096-col row.
// Saturation via occupancy: many blocks/SM, each thread holds 4 independent
// loads -> far above the Little's-law in-flight requirement for peak HBM.
__global__ void scan_kernel(const float* __restrict__ adj,
                            const float* __restrict__ x,
                            const float* __restrict__ comms,
                            const float* __restrict__ Wr,
                            const float* __restrict__ br,
                            const float* __restrict__ We,
                            const float* __restrict__ be,
                            const float* __restrict__ w_emb,
                            const float* __restrict__ b_emb)
{
    const int i    = blockIdx.x;
    const int tid  = threadIdx.x;
    const int lane = tid & 31;
    const int wid  = tid >> 5;
    __shared__ int s_wt[8];            // per-warp nonzero totals

    const float4* row = reinterpret_cast<const float4*>(adj + (size_t)i * Nn);
    // 4 independent loads (positions q*256+tid, q=0..3)
    float4 v0 = row[0 * 256 + tid];
    float4 v1 = row[1 * 256 + tid];
    float4 v2 = row[2 * 256 + tid];
    float4 v3 = row[3 * 256 + tid];

    unsigned m = 0;
    #define MB(v, q)                                          \
        m |= (unsigned)(v.x != 0.f) << (q * 4 + 0);           \
        m |= (unsigned)(v.y != 0.f) << (q * 4 + 1);           \
        m |= (unsigned)(v.z != 0.f) << (q * 4 + 2);           \
        m |= (unsigned)(v.w != 0.f) << (q * 4 + 3);
    MB(v0, 0) MB(v1, 1) MB(v2, 2) MB(v3, 3)
    #undef MB

    int c = __popc(m);
    int inc = c;                       // inclusive warp scan
    #pragma unroll
    for (int o = 1; o < 32; o <<= 1) {
        int t = __shfl_up_sync(0xffffffffu, inc, o);
        if (lane >= o) inc += t;
    }
    if (lane == 31) s_wt[wid] = inc;
    __syncthreads();

    int wpre = 0, total = 0;
    #pragma unroll
    for (int w = 0; w < 8; w++) {
        int t = s_wt[w];
        if (w < wid) wpre += t;
        total += t;
    }

    unsigned short* gc = g_colsU + (size_t)i * CAP;
    {
        unsigned mm = m;
        int p = wpre + inc - c;
        const int colbase = tid * 4;
        while (mm) {
            int b = __ffs(mm) - 1;
            mm &= mm - 1;
            int col = (b >> 2) * 1024 + colbase + (b & 3);
            if (p < CAP - 1) gc[p] = (unsigned short)col;
            p++;
        }
    }

    // warp 0: per-node features
    if (tid < 32) {
        int d = lane;                                  // 0..31 over concat(x,comms)
        float xc = (d < 16) ? x[i * 16 + d] : comms[i * 16 + (d - 16)];
        float wc = 0.f;
        #pragma unroll
        for (int c8 = 0; c8 < 8; c8++) wc += We[d * 8 + c8] * w_emb[c8];
        float rp = xc * Wr[d];
        float sp = xc * wc;
        #pragma unroll
        for (int o = 16; o > 0; o >>= 1) {
            rp += __shfl_down_sync(0xffffffffu, rp, o);
            sp += __shfl_down_sync(0xffffffffu, sp, o);
        }
        if (lane == 0) {
            int cnt = min(total, CAP - 1);
            gc[cnt] = (unsigned short)i;               // self-loop (A + I)
            cnt++;
            g_cnt[i] = cnt;
            float dinv = sqrtf(1.f / ((float)cnt + EPSF));
            float bec = 0.f;
            #pragma unroll
            for (int c8 = 0; c8 < 8; c8++) bec += be[c8] * w_emb[c8];
            float s = sp + bec;
            g_r[i]  = rp + br[0];
            g_s[i]  = s;
            g_de[i] = make_float2(dinv, dinv * (s + b_emb[0]));
        }
    }
}

// ==================================================================
// Symmetric one-hop grid barrier over NB=64 blocks: every block stores its
// flag and polls all 64 flags itself (2 coalesced L2 lines). nanosleep
// backoff keeps the spin bounded and scheduler-friendly.
__device__ __forceinline__ void sbar(int gen)
{
    __syncthreads();
    if (threadIdx.x == 0) {
        __threadfence();
        g_flag[blockIdx.x] = gen;
    }
    if (threadIdx.x < NB) {
        while (g_flag[threadIdx.x] < gen) { __nanosleep(20); }
        __threadfence();
    }
    __syncthreads();
}

// Kernel 2: persistent value iteration. 64 blocks x 512 threads.
__global__ void __launch_bounds__(ITHR, 1)
iter_kernel(const float* __restrict__ mask,
            const float* __restrict__ Wa,
            const float* __restrict__ ba,
            const int*   __restrict__ kp,
            float*       __restrict__ out)
{
    extern __shared__ char sm[];
    float*          s_u    = (float*)(sm + OFF_U);
    float*          s_W    = (float*)(sm + OFF_W);
    unsigned short* s_cols = (unsigned short*)(sm + OFF_COLS);
    float*          s_r    = (float*)(sm + OFF_R);
    float*          s_s    = (float*)(sm + OFF_S);
    float*          s_dinv = (float*)(sm + OFF_DINV);
    float*          s_v    = (float*)(sm + OFF_V);
    int*            s_cnt  = (int*)(sm + OFF_CNT);
    float*          s_Wa   = (float*)(sm + OFF_WA);
    float*          s_ba   = (float*)(sm + OFF_BA);

    const int tid  = threadIdx.x;
    const int base = blockIdx.x * NPB;

    // ---- prologue: copy this block's edge lists global -> shared (int4) ----
    {
        const int4* src = (const int4*)(g_colsU + (size_t)base * CAP);
        int4* dst = (int4*)s_cols;
        const int n16 = NPB * CAP * 2 / 16;          // 1280
        for (int q = tid; q < n16; q += ITHR) dst[q] = src[q];
    }
    if (tid < NPB) {
        int i = base + tid;
        s_r[tid]    = g_r[i];
        s_s[tid]    = g_s[i];
        s_dinv[tid] = g_de[i].x;
        s_cnt[tid]  = min(g_cnt[i], CAP);
        s_v[tid]    = 0.f;
    }
    if (tid >= NPB && tid < NPB + 8) {
        s_Wa[tid - NPB] = Wa[tid - NPB];
        s_ba[tid - NPB] = ba[tid - NPB];
    }
    __syncthreads();

    // ---- static edge weights W_ij = dinv_i * (e_j - s_i * d_j) -------------
    const int nl  = tid / TPN;
    const int sub = tid % TPN;
    const int cnt = s_cnt[nl];
    const float dinv_i = s_dinv[nl];
    const float si     = s_s[nl];
    const unsigned short* sc = s_cols + nl * CAP;
    float* sw = s_W + nl * CAP;
    for (int e = sub; e < cnt; e += TPN) {
        float2 de = __ldcg(&g_de[sc[e]]);
        sw[e] = dinv_i * fmaf(-si, de.x, de.y);
    }
    __syncthreads();

    // ---- value iteration ---------------------------------------------------
    int kk = kp[0];
    if (kk < 0 || kk > 100000) {
        float kf = __int_as_float(kk);
        kk = (kf > 0.f && kf < 100000.f) ? (int)(kf + 0.5f) : 0;
    }

    int buf = 0;
    for (int it = 0; it < kk; it++) {
        if (tid < NPB) {
            g_u[buf][base + tid] = fmaf(GAMMA_F, s_v[tid], s_r[tid]);
        }
        sbar(it + 1);

        // stage full u vector into shared (coalesced float4, L1-bypass)
        {
            const float4* src = reinterpret_cast<const float4*>(g_u[buf]);
            float4* dst = reinterpret_cast<float4*>(s_u);
            dst[tid]        = __ldcg(src + tid);
            dst[tid + ITHR] = __ldcg(src + tid + ITHR);
        }
        __syncthreads();

        float S = 0.f;
        for (int e = sub; e < cnt; e += TPN) {
            S = fmaf(sw[e], s_u[sc[e]], S);
        }
        #pragma unroll
        for (int o = TPN / 2; o > 0; o >>= 1)
            S += __shfl_down_sync(0xffffffffu, S, o, TPN);
        if (sub == 0) {
            float v = -INFINITY;
            #pragma unroll
            for (int c = 0; c < 8; c++) v = fmaxf(v, fmaf(S, s_Wa[c], s_ba[c]));
            s_v[nl] = v;
        }
        __syncthreads();
        buf ^= 1;
    }

    // ---- output + flag reset for next graph replay -------------------------
    if (tid < NPB) {
        int i = base + tid;
        out[i] = (mask[i] == 0.f) ? -INFINITY : s_v[tid];
    }
    __syncthreads();
    if (tid == 0) {
        __threadfence();
        int d = atomicAdd(&g_done, 1);
        if (d == NB - 1) {            // last block: everyone is past all polls
            for (int j = 0; j < NB; j++) g_flag[j] = 0;
            g_done = 0;
            __threadfence();
        }
    }
}

// ------------------------------------------------------------------
extern "C" void kernel_launch(void* const* d_in, const int* in_sizes, int n_in,
                              void* d_out, int out_size)
{
    const float* x     = (const float*)d_in[0];
    const float* comms = (const float*)d_in[1];
    const float* adj   = (const float*)d_in[2];
    const float* mask  = (const float*)d_in[3];
    const float* Wr    = (const float*)d_in[4];
    const float* br    = (const float*)d_in[5];
    const float* We    = (const float*)d_in[6];
    const float* be    = (const float*)d_in[7];
    const float* w_emb = (const float*)d_in[8];
    const float* b_emb = (const float*)d_in[9];
    const float* Wa    = (const float*)d_in[10];
    const float* ba    = (const float*)d_in[11];
    const int*   kp    = (const int*)d_in[12];
    float* out = (float*)d_out;

    cudaFuncSetAttribute(iter_kernel,
                         cudaFuncAttributeMaxDynamicSharedMemorySize, ISMEM);
    scan_kernel<<<Nn, 256>>>(adj, x, comms, Wr, br, We, be, w_emb, b_emb);
    iter_kernel<<<NB, ITHR, ISMEM>>>(mask, Wa, ba, kp, out);
}

// round 13
// speedup vs baseline: 1.0184x; 1.0184x over previous
#include <cuda_runtime.h>
#include <math.h>
#include <stdint.h>

#define Nn    4096
#define CAP   160                  // per-node edge capacity (mean deg ~41)
#define GAMMA_F 0.99f
#define EPSF  1.1920929e-07f

// ---- iterate kernel shape ----
#define NB    64                   // blocks (1/SM)
#define ITHR  512
#define NPB   (Nn / NB)            // 64 nodes per block
#define TPN   (ITHR / NPB)         // 8 threads per node

// ---- dynamic smem layout for iterate (bytes) ----
#define OFF_U     0                      // 16384
#define OFF_W     16384                  // 64*CAP*4 = 40960
#define OFF_COLS  57344                  // 64*CAP*2 = 20480
#define OFF_R     77824                  // 256
#define OFF_S     78080
#define OFF_DINV  78336
#define OFF_V     78592
#define OFF_CNT   78848
#define OFF_WA    79104
#define OFF_BA    79168
#define ISMEM     79232

// ---- scratch (static device globals; no allocations anywhere) ----
__device__ unsigned short g_colsU[(size_t)Nn * CAP];
__device__ int    g_cnt[Nn];
__device__ float  g_r[Nn];
__device__ float  g_s[Nn];
__device__ float2 g_de[Nn];            // (dinv_j, dinv_j*(s_j+bemb))
__device__ float  g_u[2][Nn];          // published u, double-buffered
__device__ int    g_flag[NB];          // per-block barrier flags (gpu-scope ops only)
__device__ int    g_done;              // end-of-kernel reset protocol

// ---- gpu-scope memory ops (NOT volatile: volatile == relaxed.sys on PTX,
// ---- and sys scope on GB300 drags the NVLink-C2C coherence fabric) --------
__device__ __forceinline__ void st_rel_gpu(int* p, int v) {
    asm volatile("st.relaxed.gpu.b32 [%0], %1;" :: "l"(p), "r"(v) : "memory");
}
__device__ __forceinline__ int ld_rlx_gpu(const int* p) {
    int v;
    asm volatile("ld.relaxed.gpu.b32 %0, [%1];" : "=r"(v) : "l"(p) : "memory");
    return v;
}
__device__ __forceinline__ void fence_gpu() {
    asm volatile("fence.acq_rel.gpu;" ::: "memory");
}

// ==================================================================
// Kernel 1: adjacency scan + feature computation. One block per row.
// 256 threads * 4 float4 = 1024 float4 = full 4096-col row.
// (measured ~9 us for 64 MB == near HBM roofline; unchanged)
__global__ void scan_kernel(const float* __restrict__ adj,
                            const float* __restrict__ x,
                            const float* __restrict__ comms,
                            const float* __restrict__ Wr,
                            const float* __restrict__ br,
                            const float* __restrict__ We,
                            const float* __restrict__ be,
                            const float* __restrict__ w_emb,
                            const float* __restrict__ b_emb)
{
    const int i    = blockIdx.x;
    const int tid  = threadIdx.x;
    const int lane = tid & 31;
    const int wid  = tid >> 5;
    __shared__ int s_wt[8];            // per-warp nonzero totals

    const float4* row = reinterpret_cast<const float4*>(adj + (size_t)i * Nn);
    float4 v0 = row[0 * 256 + tid];
    float4 v1 = row[1 * 256 + tid];
    float4 v2 = row[2 * 256 + tid];
    float4 v3 = row[3 * 256 + tid];

    unsigned m = 0;
    #define MB(v, q)                                          \
        m |= (unsigned)(v.x != 0.f) << (q * 4 + 0);           \
        m |= (unsigned)(v.y != 0.f) << (q * 4 + 1);           \
        m |= (unsigned)(v.z != 0.f) << (q * 4 + 2);           \
        m |= (unsigned)(v.w != 0.f) << (q * 4 + 3);
    MB(v0, 0) MB(v1, 1) MB(v2, 2) MB(v3, 3)
    #undef MB

    int c = __popc(m);
    int inc = c;                       // inclusive warp scan
    #pragma unroll
    for (int o = 1; o < 32; o <<= 1) {
        int t = __shfl_up_sync(0xffffffffu, inc, o);
        if (lane >= o) inc += t;
    }
    if (lane == 31) s_wt[wid] = inc;
    __syncthreads();

    int wpre = 0, total = 0;
    #pragma unroll
    for (int w = 0; w < 8; w++) {
        int t = s_wt[w];
        if (w < wid) wpre += t;
        total += t;
    }

    unsigned short* gc = g_colsU + (size_t)i * CAP;
    {
        unsigned mm = m;
        int p = wpre + inc - c;
        const int colbase = tid * 4;
        while (mm) {
            int b = __ffs(mm) - 1;
            mm &= mm - 1;
            int col = (b >> 2) * 1024 + colbase + (b & 3);
            if (p < CAP - 1) gc[p] = (unsigned short)col;
            p++;
        }
    }

    // warp 0: per-node features
    if (tid < 32) {
        int d = lane;                                  // 0..31 over concat(x,comms)
        float xc = (d < 16) ? x[i * 16 + d] : comms[i * 16 + (d - 16)];
        float wc = 0.f;
        #pragma unroll
        for (int c8 = 0; c8 < 8; c8++) wc += We[d * 8 + c8] * w_emb[c8];
        float rp = xc * Wr[d];
        float sp = xc * wc;
        #pragma unroll
        for (int o = 16; o > 0; o >>= 1) {
            rp += __shfl_down_sync(0xffffffffu, rp, o);
            sp += __shfl_down_sync(0xffffffffu, sp, o);
        }
        if (lane == 0) {
            int cnt = min(total, CAP - 1);
            gc[cnt] = (unsigned short)i;               // self-loop (A + I)
            cnt++;
            g_cnt[i] = cnt;
            float dinv = sqrtf(1.f / ((float)cnt + EPSF));
            float bec = 0.f;
            #pragma unroll
            for (int c8 = 0; c8 < 8; c8++) bec += be[c8] * w_emb[c8];
            float s = sp + bec;
            g_r[i]  = rp + br[0];
            g_s[i]  = s;
            g_de[i] = make_float2(dinv, dinv * (s + b_emb[0]));
        }
    }
}

// ==================================================================
// Symmetric one-hop grid barrier over NB=64 blocks, gpu-scope only:
// each block publishes its flag (release via fence), every block polls
// all 64 flags itself (2 coalesced L2 lines), one acquire fence on exit.
__device__ __forceinline__ void sbar(int gen)
{
    __syncthreads();
    if (threadIdx.x == 0) {
        fence_gpu();                              // release prior block stores
        st_rel_gpu(&g_flag[blockIdx.x], gen);
    }
    if (threadIdx.x < NB) {
        while (ld_rlx_gpu(&g_flag[threadIdx.x]) < gen) { }
        fence_gpu();                              // acquire
    }
    __syncthreads();
}

// Kernel 2: persistent value iteration. 64 blocks x 512 threads.
__global__ void __launch_bounds__(ITHR, 1)
iter_kernel(const float* __restrict__ mask,
            const float* __restrict__ Wa,
            const float* __restrict__ ba,
            const int*   __restrict__ kp,
            float*       __restrict__ out)
{
    extern __shared__ char sm[];
    float*          s_u    = (float*)(sm + OFF_U);
    float*          s_W    = (float*)(sm + OFF_W);
    unsigned short* s_cols = (unsigned short*)(sm + OFF_COLS);
    float*          s_r    = (float*)(sm + OFF_R);
    float*          s_s    = (float*)(sm + OFF_S);
    float*          s_dinv = (float*)(sm + OFF_DINV);
    float*          s_v    = (float*)(sm + OFF_V);
    int*            s_cnt  = (int*)(sm + OFF_CNT);
    float*          s_Wa   = (float*)(sm + OFF_WA);
    float*          s_ba   = (float*)(sm + OFF_BA);

    const int tid  = threadIdx.x;
    const int base = blockIdx.x * NPB;

    // ---- prologue: copy this block's edge lists global -> shared (int4) ----
    {
        const int4* src = (const int4*)(g_colsU + (size_t)base * CAP);
        int4* dst = (int4*)s_cols;
        const int n16 = NPB * CAP * 2 / 16;          // 1280
        for (int q = tid; q < n16; q += ITHR) dst[q] = src[q];
    }
    if (tid < NPB) {
        int i = base + tid;
        s_r[tid]    = g_r[i];
        s_s[tid]    = g_s[i];
        s_dinv[tid] = g_de[i].x;
        s_cnt[tid]  = min(g_cnt[i], CAP);
        s_v[tid]    = 0.f;
    }
    if (tid >= NPB && tid < NPB + 8) {
        s_Wa[tid - NPB] = Wa[tid - NPB];
        s_ba[tid - NPB] = ba[tid - NPB];
    }
    __syncthreads();

    // ---- static edge weights W_ij = dinv_i * (e_j - s_i * d_j) -------------
    const int nl  = tid / TPN;
    const int sub = tid % TPN;
    const int cnt = s_cnt[nl];
    const float dinv_i = s_dinv[nl];
    const float si     = s_s[nl];
    const unsigned short* sc = s_cols + nl * CAP;
    float* sw = s_W + nl * CAP;
    for (int e = sub; e < cnt; e += TPN) {
        float2 de = __ldcg(&g_de[sc[e]]);
        sw[e] = dinv_i * fmaf(-si, de.x, de.y);
    }
    __syncthreads();

    // ---- value iteration ---------------------------------------------------
    int kk = kp[0];
    if (kk < 0 || kk > 100000) {
        float kf = __int_as_float(kk);
        kk = (kf > 0.f && kf < 100000.f) ? (int)(kf + 0.5f) : 0;
    }

    int buf = 0;
    for (int it = 0; it < kk; it++) {
        // publish u = r + gamma*v (16 threads x float4, fewer stores to ack)
        if (tid < NPB / 4) {
            const float4 v4 = ((const float4*)s_v)[tid];
            const float4 r4 = ((const float4*)s_r)[tid];
            float4 u4;
            u4.x = fmaf(GAMMA_F, v4.x, r4.x);
            u4.y = fmaf(GAMMA_F, v4.y, r4.y);
            u4.z = fmaf(GAMMA_F, v4.z, r4.z);
            u4.w = fmaf(GAMMA_F, v4.w, r4.w);
            ((float4*)(g_u[buf] + base))[tid] = u4;
        }
        sbar(it + 1);

        // stage full u vector into shared (coalesced float4, L1-bypass)
        {
            const float4* src = reinterpret_cast<const float4*>(g_u[buf]);
            float4* dst = reinterpret_cast<float4*>(s_u);
            dst[tid]        = __ldcg(src + tid);
            dst[tid + ITHR] = __ldcg(src + tid + ITHR);
        }
        __syncthreads();

        float S = 0.f;
        for (int e = sub; e < cnt; e += TPN) {
            S = fmaf(sw[e], s_u[sc[e]], S);
        }
        #pragma unroll
        for (int o = TPN / 2; o > 0; o >>= 1)
            S += __shfl_down_sync(0xffffffffu, S, o, TPN);
        if (sub == 0) {
            float v = -INFINITY;
            #pragma unroll
            for (int c = 0; c < 8; c++) v = fmaxf(v, fmaf(S, s_Wa[c], s_ba[c]));
            s_v[nl] = v;
        }
        __syncthreads();
        buf ^= 1;
    }

    // ---- output + flag reset for next graph replay -------------------------
    if (tid < NPB) {
        int i = base + tid;
        out[i] = (mask[i] == 0.f) ? -INFINITY : s_v[tid];
    }
    __syncthreads();
    if (tid == 0) {
        int d = atomicAdd(&g_done, 1);
        if (d == NB - 1) {            // last block: everyone is past all polls
            for (int j = 0; j < NB; j++) g_flag[j] = 0;
            g_done = 0;
            fence_gpu();
        }
    }
}

// ------------------------------------------------------------------
extern "C" void kernel_launch(void* const* d_in, const int* in_sizes, int n_in,
                              void* d_out, int out_size)
{
    const float* x     = (const float*)d_in[0];
    const float* comms = (const float*)d_in[1];
    const float* adj   = (const float*)d_in[2];
    const float* mask  = (const float*)d_in[3];
    const float* Wr    = (const float*)d_in[4];
    const float* br    = (const float*)d_in[5];
    const float* We    = (const float*)d_in[6];
    const float* be    = (const float*)d_in[7];
    const float* w_emb = (const float*)d_in[8];
    const float* b_emb = (const float*)d_in[9];
    const float* Wa    = (const float*)d_in[10];
    const float* ba    = (const float*)d_in[11];
    const int*   kp    = (const int*)d_in[12];
    float* out = (float*)d_out;

    cudaFuncSetAttribute(iter_kernel,
                         cudaFuncAttributeMaxDynamicSharedMemorySize, ISMEM);
    scan_kernel<<<Nn, 256>>>(adj, x, comms, Wr, br, We, be, w_emb, b_emb);
    iter_kernel<<<NB, ITHR, ISMEM>>>(mask, Wa, ba, kp, out);
}